// round 5
// baseline (speedup 1.0000x reference)
#include <cuda_runtime.h>
#include <cuda_bf16.h>

#define FEAT   24
#define NPIX   (FEAT*FEAT)        // 576
#define KANCH  9
#define NN     (NPIX*KANCH)       // 5184
#define MIDCH  24
#define CINCH  512
#define NWORD  81                 // 5184 / 64
#define NCH    41                 // chunks of 128 rows (last = 64 rows)
#define IMGW   384.0f
#define IMGH   384.0f
#define NMS_T  0.7f
#define MINSZ  16.0f
#define KCHUNKS 16                // 512 / 32
#define CPART  32

typedef unsigned long long u64;

// ---------------- scratch (device globals; no allocation allowed) -------------
__device__ float g_hpart[KCHUNKS * MIDCH * NPIX];

__device__ float g_x0[NN], g_y0[NN], g_x1[NN], g_y1[NN];
__device__ float g_ws[NN], g_hs[NN], g_prob[NN];
__device__ unsigned g_valid[NN];
__device__ u64 g_keys[NN];

__device__ float g_bx0[NN], g_by0[NN], g_bx1[NN], g_by1[NN], g_barea[NN];
__device__ unsigned g_bvalid[NN];
__device__ int g_order[NN];

__device__ u64 g_mask[NN * NWORD];

// ---------------- 1. conv 3x3, 512->24, partial over K chunks -----------------
__global__ void conv_part_kernel(const float* __restrict__ x,
                                 const float* __restrict__ W) {
    const int y  = blockIdx.x;          // 0..23
    const int kc = blockIdx.y;          // 0..15
    const int c0 = kc * CPART;

    __shared__ float xs[CPART][3][26];
    __shared__ float ws[MIDCH][CPART][9];

    const int tid = threadIdx.x;        // 576 threads

    for (int idx = tid; idx < CPART * 3 * 26; idx += 576) {
        int c  = idx / 78;
        int r  = (idx % 78) / 26;
        int xx = idx % 26;
        int gy = y + r - 1;
        int gx = xx - 1;
        float v = 0.0f;
        if (gy >= 0 && gy < FEAT && gx >= 0 && gx < FEAT)
            v = x[(c0 + c) * NPIX + gy * FEAT + gx];
        xs[c][r][xx] = v;
    }
    for (int idx = tid; idx < MIDCH * CPART * 9; idx += 576) {
        int o = idx / (CPART * 9);
        int c = (idx % (CPART * 9)) / 9;
        int t = idx % 9;
        ws[o][c][t] = W[((o * CINCH) + c0 + c) * 9 + t];
    }
    __syncthreads();

    const int xc = tid % FEAT;
    const int o  = tid / FEAT;
    float acc = 0.0f;
    #pragma unroll 4
    for (int c = 0; c < CPART; c++) {
        float a0 = xs[c][0][xc], a1 = xs[c][0][xc+1], a2 = xs[c][0][xc+2];
        float b0 = xs[c][1][xc], b1 = xs[c][1][xc+1], b2 = xs[c][1][xc+2];
        float d0 = xs[c][2][xc], d1 = xs[c][2][xc+1], d2 = xs[c][2][xc+2];
        const float* w = ws[o][c];
        acc += a0*w[0] + a1*w[1] + a2*w[2]
             + b0*w[3] + b1*w[4] + b2*w[5]
             + d0*w[6] + d1*w[7] + d2*w[8];
    }
    g_hpart[kc * (MIDCH*NPIX) + o * NPIX + y * FEAT + xc] = acc;
}

// ---------------- 2. heads + decode (conv-reduce fused) -----------------------
__global__ __launch_bounds__(288) void decode_kernel(
        const float* __restrict__ Wc, const float* __restrict__ bc,
        const float* __restrict__ Wr, const float* __restrict__ br,
        const float* __restrict__ brpn,
        const float* __restrict__ anchors,
        float* __restrict__ out) {
    __shared__ float sh[32][MIDCH];
    __shared__ float sWc[2*KANCH*MIDCH];
    __shared__ float sWr[4*KANCH*MIDCH];
    __shared__ float sbc[2*KANCH];
    __shared__ float sbr[4*KANCH];

    const int tid = threadIdx.x;
    const int p0  = blockIdx.x * 32;

    for (int i = tid; i < 32 * MIDCH; i += 288) {
        int ch = i / 32, pp = i % 32;
        float s = 0.0f;
        #pragma unroll
        for (int kc = 0; kc < KCHUNKS; kc++)
            s += g_hpart[kc * (MIDCH*NPIX) + ch * NPIX + p0 + pp];
        sh[pp][ch] = fmaxf(s + brpn[ch], 0.0f);
    }
    for (int i = tid; i < 2*KANCH*MIDCH; i += 288) sWc[i] = Wc[i];
    for (int i = tid; i < 4*KANCH*MIDCH; i += 288) sWr[i] = Wr[i];
    if (tid < 2*KANCH) sbc[tid] = bc[tid];
    if (tid < 4*KANCH) sbr[tid] = br[tid];
    __syncthreads();

    const int lp = tid / KANCH;          // 0..31
    const int k  = tid % KANCH;
    const int n  = (p0 + lp) * KANCH + k;

    float hv[MIDCH];
    #pragma unroll
    for (int o = 0; o < MIDCH; o++) hv[o] = sh[lp][o];

    float c0 = 0.0f, c1 = 0.0f;
    #pragma unroll
    for (int o = 0; o < MIDCH; o++) {
        c0 += hv[o] * sWc[(2*k)   * MIDCH + o];
        c1 += hv[o] * sWc[(2*k+1) * MIDCH + o];
    }
    c0 += sbc[2*k]; c1 += sbc[2*k+1];

    float tx = 0.0f, ty = 0.0f, tw = 0.0f, th = 0.0f;
    #pragma unroll
    for (int o = 0; o < MIDCH; o++) {
        float h = hv[o];
        tx += h * sWr[(4*k)   * MIDCH + o];
        ty += h * sWr[(4*k+1) * MIDCH + o];
        tw += h * sWr[(4*k+2) * MIDCH + o];
        th += h * sWr[(4*k+3) * MIDCH + o];
    }
    tx += sbr[4*k]; ty += sbr[4*k+1]; tw += sbr[4*k+2]; th += sbr[4*k+3];

    out[4*NN + 2*n]     = c0;
    out[4*NN + 2*n + 1] = c1;
    float prob = 1.0f / (1.0f + expf(c0 - c1));

    float ax = anchors[4*n],   ay = anchors[4*n+1];
    float aw = anchors[4*n+2], ah = anchors[4*n+3];

    float px = ax + aw * tx;
    float py = ay + ah * ty;
    float pw = aw * expf(tw);
    float ph = ah * expf(th);
    out[4*n]   = px; out[4*n+1] = py;
    out[4*n+2] = pw; out[4*n+3] = ph;

    float x0 = px - 0.5f * (pw - 1.0f);
    float y0 = py - 0.5f * (ph - 1.0f);
    float x1 = pw + x0 - 1.0f;
    float y1 = ph + y0 - 1.0f;
    x0 = fminf(fmaxf(x0, 0.0f), IMGW - 1.0f);
    x1 = fminf(fmaxf(x1, 0.0f), IMGW - 1.0f);
    y0 = fminf(fmaxf(y0, 0.0f), IMGH - 1.0f);
    y1 = fminf(fmaxf(y1, 0.0f), IMGH - 1.0f);
    float wsv = x1 - x0 + 1.0f;
    float hsv = y1 - y0 + 1.0f;

    float ax0 = ax - 0.5f * (aw - 1.0f);
    float ay0 = ay - 0.5f * (ah - 1.0f);
    float ax1 = aw + ax0 - 1.0f;
    float ay1 = ah + ay0 - 1.0f;
    bool anchor_valid = (ax0 >= 0.0f) && (ay0 >= 0.0f) && (ax1 < IMGW) && (ay1 < IMGH);
    bool valid = anchor_valid && (wsv >= MINSZ) && (hsv >= MINSZ);

    float score = valid ? prob : -1.0f;
    float f = -score;
    unsigned u = __float_as_uint(f);
    u = (u & 0x80000000u) ? ~u : (u | 0x80000000u);
    g_keys[n] = ((u64)u << 32) | (unsigned)n;

    g_x0[n] = x0; g_y0[n] = y0; g_x1[n] = x1; g_y1[n] = y1;
    g_ws[n] = wsv; g_hs[n] = hsv; g_prob[n] = prob;
    g_valid[n] = valid ? 1u : 0u;
}

// ---------------- 3. fused rank-by-counting + scatter --------------------------
// 18 blocks x 288 threads; all keys in smem, thread i ranks key i, scatters box
__global__ __launch_bounds__(288) void ranksort_kernel() {
    __shared__ u64 sk[NN];               // 41472 B static
    const int tid = threadIdx.x;
    for (int j = tid; j < NN; j += 288) sk[j] = g_keys[j];
    __syncthreads();

    const int i = blockIdx.x * 288 + tid;
    const u64 key = sk[i];
    int cnt = 0;
    #pragma unroll 8
    for (int j = 0; j < NN; j++) cnt += (sk[j] < key) ? 1 : 0;

    g_order[cnt]  = i;
    g_bx0[cnt]    = g_x0[i];
    g_by0[cnt]    = g_y0[i];
    g_bx1[cnt]    = g_x1[i];
    g_by1[cnt]    = g_y1[i];
    g_barea[cnt]  = g_ws[i] * g_hs[i];
    g_bvalid[cnt] = g_valid[i];
}

// ---------------- 4. suppression bitmask matrix (upper triangle only) ----------
__global__ void mask_kernel() {
    const int rb = blockIdx.y, cb = blockIdx.x;
    if (cb < rb) return;
    const int t  = threadIdx.x;          // 64 threads
    const int i  = rb * 64 + t;

    __shared__ float cx0[64], cy0[64], cx1[64], cy1[64], car[64];
    {
        int j = cb * 64 + t;
        cx0[t] = g_bx0[j]; cy0[t] = g_by0[j];
        cx1[t] = g_bx1[j]; cy1[t] = g_by1[j];
        car[t] = g_barea[j];
    }
    __syncthreads();

    u64 w = 0ull;
    if (g_bvalid[i]) {
        float x0 = g_bx0[i], y0 = g_by0[i], x1 = g_bx1[i], y1 = g_by1[i];
        float ar = g_barea[i];
        int jbase = cb * 64;
        #pragma unroll 8
        for (int b = 0; b < 64; b++) {
            int j = jbase + b;
            if (j > i) {
                float iw = fminf(x1, cx1[b]) - fmaxf(x0, cx0[b]) + 1.0f;
                float ih = fminf(y1, cy1[b]) - fmaxf(y0, cy0[b]) + 1.0f;
                iw = fmaxf(iw, 0.0f);
                ih = fmaxf(ih, 0.0f);
                float inter = iw * ih;
                float iou = inter / (ar + car[b] - inter);
                if (iou > NMS_T) w |= (1ull << b);
            }
        }
    }
    g_mask[(size_t)i * NWORD + cb] = w;
}

// ---------------- 5. pipelined greedy NMS + fused finalize ---------------------
// 128-row chunks. Per iteration, concurrently:
//   tid 0       : greedy scan of chunk t (smem), fused update of remv_s[2t+2,3]
//   tid 32..127 : bulk remv_b update for chunk t-1 kept rows, words >= 2t+2
//   tid 128..511: prefetch chunk t+1 diag block (words 2t+2..2t+5) into smem
// remv_scan / remv_bulk are separate accumulators -> no RMW race.
#define RT 512
__global__ __launch_bounds__(RT) void nms_kernel(
        const int* __restrict__ labels, float* __restrict__ out) {
    __shared__ u64 sblk[2][128][4];      // double-buffered 128x256-bit blocks
    __shared__ u64 remv_s[NWORD + 2];
    __shared__ u64 remv_b[NWORD + 2];
    __shared__ u64 vword[NWORD + 1];
    __shared__ u64 skw[NWORD + 1];       // keep bits, sorted order
    __shared__ int kb[2][128];
    __shared__ int kcnt[2];
    __shared__ unsigned vhalf[NWORD * 2];

    const int tid  = threadIdx.x;
    const int lane = tid & 31;

    for (int w = tid; w < NWORD + 2; w += RT) { remv_s[w] = 0ull; remv_b[w] = 0ull; }
    for (int i = tid; i < NN; i += RT) {
        unsigned bal = __ballot_sync(0xFFFFFFFFu, g_bvalid[i] != 0u);
        if (lane == 0) vhalf[i >> 5] = bal;
    }
    if (tid == 0) { vword[NWORD] = 0ull; kcnt[0] = 0; kcnt[1] = 0; }
    __syncthreads();
    for (int w = tid; w < NWORD; w += RT)
        vword[w] = ((u64)vhalf[2*w+1] << 32) | (u64)vhalf[2*w];

    // prefetch chunk 0 (rows 0..127, words 0..3)
    for (int e = tid; e < 512; e += RT) {
        int r = e >> 2, wq = e & 3;
        sblk[0][r][wq] = g_mask[(size_t)r * NWORD + wq];
    }
    __syncthreads();

    for (int t = 0; t < NCH; t++) {
        const int p  = t & 1;
        const int bR = t * 128;

        if (tid == 0) {
            // -------- greedy scan of chunk t --------
            u64 avail0 = vword[2*t]   & ~(remv_s[2*t]   | remv_b[2*t]);
            u64 avail1 = vword[2*t+1] & ~(remv_s[2*t+1] | remv_b[2*t+1]);
            u64 k0 = 0ull, k1 = 0ull, r2 = 0ull, r3 = 0ull;
            int n = 0;
            while (avail0 | avail1) {
                int b;
                if (avail0) {
                    b = __ffsll((long long)avail0) - 1;
                    k0 |= (1ull << b);
                    avail0 &= ~(1ull << b);
                } else {
                    int bb = __ffsll((long long)avail1) - 1;
                    b = 64 + bb;
                    k1 |= (1ull << bb);
                    avail1 &= ~(1ull << bb);
                }
                const u64* dd = sblk[p][b];
                avail0 &= ~dd[0];
                avail1 &= ~dd[1];
                r2 |= dd[2];
                r3 |= dd[3];
                kb[p][n++] = b;
            }
            kcnt[p] = n;
            skw[2*t]   = k0;
            skw[2*t+1] = k1;
            if (2*t+2 < NWORD) remv_s[2*t+2] |= r2;
            if (2*t+3 < NWORD) remv_s[2*t+3] |= r3;
        } else if (tid < 128) {
            // -------- bulk update for chunk t-1 --------
            if (t > 0) {
                const int np = kcnt[p ^ 1];
                if (np > 0) {
                    const int bRp = (t - 1) * 128;
                    const int* kbp = kb[p ^ 1];
                    for (int w = 2*t + 2 + (tid - 32); w < NWORD; w += 96) {
                        u64 acc = 0ull;
                        int q = 0;
                        for (; q + 4 <= np; q += 4) {
                            u64 a0 = g_mask[(size_t)(bRp + kbp[q])   * NWORD + w];
                            u64 a1 = g_mask[(size_t)(bRp + kbp[q+1]) * NWORD + w];
                            u64 a2 = g_mask[(size_t)(bRp + kbp[q+2]) * NWORD + w];
                            u64 a3 = g_mask[(size_t)(bRp + kbp[q+3]) * NWORD + w];
                            acc |= a0 | a1 | a2 | a3;
                        }
                        for (; q < np; q++)
                            acc |= g_mask[(size_t)(bRp + kbp[q]) * NWORD + w];
                        remv_b[w] |= acc;
                    }
                }
            }
        } else {
            // -------- prefetch chunk t+1 block --------
            const int tt = t + 1;
            if (tt < NCH) {
                const int bR2 = tt * 128;
                for (int e = tid - 128; e < 512; e += RT - 128) {
                    int r = e >> 2, wq = e & 3;
                    int row = bR2 + r;
                    int gw  = 2*tt + wq;
                    u64 v = 0ull;
                    if (row < NN && gw < NWORD)
                        v = g_mask[(size_t)row * NWORD + gw];
                    sblk[p ^ 1][r][wq] = v;
                }
            }
        }
        __syncthreads();
    }

    // -------- fused finalize --------
    for (int i = tid; i < NN; i += RT) {
        int nidx = g_order[i];
        unsigned kp = (unsigned)((skw[i >> 6] >> (i & 63)) & 1ull);
        float kf = kp ? 1.0f : 0.0f;
        float x0 = g_x0[nidx], y0 = g_y0[nidx];
        float wsv = g_ws[nidx], hsv = g_hs[nidx];
        out[6*NN + 4*nidx]     = (x0 + 0.5f * (wsv - 1.0f)) * kf;
        out[6*NN + 4*nidx + 1] = (y0 + 0.5f * (hsv - 1.0f)) * kf;
        out[6*NN + 4*nidx + 2] = wsv * kf;
        out[6*NN + 4*nidx + 3] = hsv * kf;
        out[10*NN + nidx] = g_prob[nidx] * kf;
        out[11*NN + nidx] = kp ? (float)labels[nidx] : 0.0f;
        out[12*NN + nidx] = kf;
    }
}

// -------------------------------------------------------------------------------
extern "C" void kernel_launch(void* const* d_in, const int* in_sizes, int n_in,
                              void* d_out, int out_size) {
    const float* x       = (const float*)d_in[0];
    const int*   labels  = (const int*)  d_in[1];
    const float* Wrpn    = (const float*)d_in[2];
    const float* brpn    = (const float*)d_in[3];
    const float* Wc      = (const float*)d_in[4];
    const float* bc      = (const float*)d_in[5];
    const float* Wr      = (const float*)d_in[6];
    const float* br      = (const float*)d_in[7];
    const float* anchors = (const float*)d_in[8];
    float* out = (float*)d_out;

    conv_part_kernel<<<dim3(FEAT, KCHUNKS), 576>>>(x, Wrpn);
    decode_kernel<<<NPIX / 32, 288>>>(Wc, bc, Wr, br, brpn, anchors, out);
    ranksort_kernel<<<18, 288>>>();
    mask_kernel<<<dim3(NWORD, NWORD), 64>>>();
    nms_kernel<<<1, RT>>>(labels, out);
}

// round 7
// speedup vs baseline: 1.9515x; 1.9515x over previous
#include <cuda_runtime.h>
#include <cuda_bf16.h>

#define FEAT   24
#define NPIX   (FEAT*FEAT)        // 576
#define KANCH  9
#define NN     (NPIX*KANCH)       // 5184
#define MIDCH  24
#define CINCH  512
#define NWORD  81                 // 5184 / 64
#define NCH    41                 // chunks of 128 rows (last = 64 rows)
#define IMGW   384.0f
#define IMGH   384.0f
#define NMS_T  0.7f
#define MINSZ  16.0f
#define KCHUNKS 16
#define CPART  32
#define NSLICE 8
#define SLICE  (NN / NSLICE)      // 648
#define TPW    6                  // bulk threads per word

typedef unsigned long long u64;

// ---------------- scratch (device globals; zero-initialized) ------------------
__device__ float g_hpart[KCHUNKS * MIDCH * NPIX];

__device__ float g_x0[NN], g_y0[NN], g_x1[NN], g_y1[NN];
__device__ float g_ws[NN], g_hs[NN], g_prob[NN];
__device__ unsigned g_valid[NN];
__device__ u64 g_keys[NN];
__device__ int g_rankpart[NSLICE * NN];

__device__ float g_bx0[NN], g_by0[NN], g_bx1[NN], g_by1[NN], g_barea[NN];
__device__ unsigned g_bvalid[NN];
__device__ int g_order[NN];

__device__ u64 g_mask[NN * NWORD];   // only valid-headed blocks ever written

// ---------------- 1. conv 3x3, 512->24, partial over K chunks -----------------
__global__ void conv_part_kernel(const float* __restrict__ x,
                                 const float* __restrict__ W) {
    const int y  = blockIdx.x;
    const int kc = blockIdx.y;
    const int c0 = kc * CPART;

    __shared__ float xs[CPART][3][26];
    __shared__ float ws[MIDCH][CPART][9];

    const int tid = threadIdx.x;        // 576

    for (int idx = tid; idx < CPART * 3 * 26; idx += 576) {
        int c  = idx / 78;
        int r  = (idx % 78) / 26;
        int xx = idx % 26;
        int gy = y + r - 1;
        int gx = xx - 1;
        float v = 0.0f;
        if (gy >= 0 && gy < FEAT && gx >= 0 && gx < FEAT)
            v = x[(c0 + c) * NPIX + gy * FEAT + gx];
        xs[c][r][xx] = v;
    }
    for (int idx = tid; idx < MIDCH * CPART * 9; idx += 576) {
        int o = idx / (CPART * 9);
        int c = (idx % (CPART * 9)) / 9;
        int t = idx % 9;
        ws[o][c][t] = W[((o * CINCH) + c0 + c) * 9 + t];
    }
    __syncthreads();

    const int xc = tid % FEAT;
    const int o  = tid / FEAT;
    float acc = 0.0f;
    #pragma unroll 4
    for (int c = 0; c < CPART; c++) {
        float a0 = xs[c][0][xc], a1 = xs[c][0][xc+1], a2 = xs[c][0][xc+2];
        float b0 = xs[c][1][xc], b1 = xs[c][1][xc+1], b2 = xs[c][1][xc+2];
        float d0 = xs[c][2][xc], d1 = xs[c][2][xc+1], d2 = xs[c][2][xc+2];
        const float* w = ws[o][c];
        acc += a0*w[0] + a1*w[1] + a2*w[2]
             + b0*w[3] + b1*w[4] + b2*w[5]
             + d0*w[6] + d1*w[7] + d2*w[8];
    }
    g_hpart[kc * (MIDCH*NPIX) + o * NPIX + y * FEAT + xc] = acc;
}

// ---------------- 2. heads + decode (conv-reduce fused) -----------------------
__global__ __launch_bounds__(288) void decode_kernel(
        const float* __restrict__ Wc, const float* __restrict__ bc,
        const float* __restrict__ Wr, const float* __restrict__ br,
        const float* __restrict__ brpn,
        const float* __restrict__ anchors,
        float* __restrict__ out) {
    __shared__ float sh[32][MIDCH];
    __shared__ float sWc[2*KANCH*MIDCH];
    __shared__ float sWr[4*KANCH*MIDCH];
    __shared__ float sbc[2*KANCH];
    __shared__ float sbr[4*KANCH];

    const int tid = threadIdx.x;
    const int p0  = blockIdx.x * 32;

    for (int i = tid; i < 32 * MIDCH; i += 288) {
        int ch = i / 32, pp = i % 32;
        float s = 0.0f;
        #pragma unroll
        for (int kc = 0; kc < KCHUNKS; kc++)
            s += g_hpart[kc * (MIDCH*NPIX) + ch * NPIX + p0 + pp];
        sh[pp][ch] = fmaxf(s + brpn[ch], 0.0f);
    }
    for (int i = tid; i < 2*KANCH*MIDCH; i += 288) sWc[i] = Wc[i];
    for (int i = tid; i < 4*KANCH*MIDCH; i += 288) sWr[i] = Wr[i];
    if (tid < 2*KANCH) sbc[tid] = bc[tid];
    if (tid < 4*KANCH) sbr[tid] = br[tid];
    __syncthreads();

    const int lp = tid / KANCH;
    const int k  = tid % KANCH;
    const int n  = (p0 + lp) * KANCH + k;

    float hv[MIDCH];
    #pragma unroll
    for (int o = 0; o < MIDCH; o++) hv[o] = sh[lp][o];

    float c0 = 0.0f, c1 = 0.0f;
    #pragma unroll
    for (int o = 0; o < MIDCH; o++) {
        c0 += hv[o] * sWc[(2*k)   * MIDCH + o];
        c1 += hv[o] * sWc[(2*k+1) * MIDCH + o];
    }
    c0 += sbc[2*k]; c1 += sbc[2*k+1];

    float tx = 0.0f, ty = 0.0f, tw = 0.0f, th = 0.0f;
    #pragma unroll
    for (int o = 0; o < MIDCH; o++) {
        float h = hv[o];
        tx += h * sWr[(4*k)   * MIDCH + o];
        ty += h * sWr[(4*k+1) * MIDCH + o];
        tw += h * sWr[(4*k+2) * MIDCH + o];
        th += h * sWr[(4*k+3) * MIDCH + o];
    }
    tx += sbr[4*k]; ty += sbr[4*k+1]; tw += sbr[4*k+2]; th += sbr[4*k+3];

    out[4*NN + 2*n]     = c0;
    out[4*NN + 2*n + 1] = c1;
    float prob = 1.0f / (1.0f + expf(c0 - c1));

    float ax = anchors[4*n],   ay = anchors[4*n+1];
    float aw = anchors[4*n+2], ah = anchors[4*n+3];

    float px = ax + aw * tx;
    float py = ay + ah * ty;
    float pw = aw * expf(tw);
    float ph = ah * expf(th);
    out[4*n]   = px; out[4*n+1] = py;
    out[4*n+2] = pw; out[4*n+3] = ph;

    float x0 = px - 0.5f * (pw - 1.0f);
    float y0 = py - 0.5f * (ph - 1.0f);
    float x1 = pw + x0 - 1.0f;
    float y1 = ph + y0 - 1.0f;
    x0 = fminf(fmaxf(x0, 0.0f), IMGW - 1.0f);
    x1 = fminf(fmaxf(x1, 0.0f), IMGW - 1.0f);
    y0 = fminf(fmaxf(y0, 0.0f), IMGH - 1.0f);
    y1 = fminf(fmaxf(y1, 0.0f), IMGH - 1.0f);
    float wsv = x1 - x0 + 1.0f;
    float hsv = y1 - y0 + 1.0f;

    float ax0 = ax - 0.5f * (aw - 1.0f);
    float ay0 = ay - 0.5f * (ah - 1.0f);
    float ax1 = aw + ax0 - 1.0f;
    float ay1 = ah + ay0 - 1.0f;
    bool anchor_valid = (ax0 >= 0.0f) && (ay0 >= 0.0f) && (ax1 < IMGW) && (ay1 < IMGH);
    bool valid = anchor_valid && (wsv >= MINSZ) && (hsv >= MINSZ);

    float score = valid ? prob : -1.0f;
    float f = -score;
    unsigned u = __float_as_uint(f);
    u = (u & 0x80000000u) ? ~u : (u | 0x80000000u);
    g_keys[n] = ((u64)u << 32) | (unsigned)n;

    g_x0[n] = x0; g_y0[n] = y0; g_x1[n] = x1; g_y1[n] = y1;
    g_ws[n] = wsv; g_hs[n] = hsv; g_prob[n] = prob;
    g_valid[n] = valid ? 1u : 0u;
}

// ---------------- 3a. rank-by-counting partials (sliced) ----------------------
__global__ __launch_bounds__(288) void rank_part_kernel() {
    __shared__ u64 sk[SLICE];
    const int tid = threadIdx.x;
    const int s   = blockIdx.y;
    const int i   = blockIdx.x * 288 + tid;

    for (int j = tid; j < SLICE; j += 288) sk[j] = g_keys[s * SLICE + j];
    __syncthreads();

    const u64 key = g_keys[i];
    int cnt = 0;
    #pragma unroll 8
    for (int j = 0; j < SLICE; j++) cnt += (sk[j] < key) ? 1 : 0;
    g_rankpart[s * NN + i] = cnt;
}

// ---------------- 3b. rank reduce + scatter ------------------------------------
__global__ void scatter_rank_kernel() {
    int i = blockIdx.x * blockDim.x + threadIdx.x;
    if (i >= NN) return;
    int r = 0;
    #pragma unroll
    for (int s = 0; s < NSLICE; s++) r += g_rankpart[s * NN + i];
    g_order[r]  = i;
    g_bx0[r]    = g_x0[i];
    g_by0[r]    = g_y0[i];
    g_bx1[r]    = g_x1[i];
    g_by1[r]    = g_y1[i];
    g_barea[r]  = g_ws[i] * g_hs[i];
    g_bvalid[r] = g_valid[i];
}

// ---------------- 4. suppression bitmask (valid-headed blocks only) ------------
// Validity is monotone in sorted order (invalid scores = -1 sort last), so a
// block is all-invalid iff its first row is invalid. Unwritten g_mask words are
// never consumed (vword masks them) and stay 0 (zero-init) -> deterministic.
__global__ void mask_kernel() {
    const int rb = blockIdx.y, cb = blockIdx.x;
    if (cb < rb) return;
    if (g_bvalid[rb * 64] == 0u || g_bvalid[cb * 64] == 0u) return;

    const int t  = threadIdx.x;          // 64 threads
    const int i  = rb * 64 + t;

    __shared__ float cx0[64], cy0[64], cx1[64], cy1[64], car[64];
    {
        int j = cb * 64 + t;
        cx0[t] = g_bx0[j]; cy0[t] = g_by0[j];
        cx1[t] = g_bx1[j]; cy1[t] = g_by1[j];
        car[t] = g_barea[j];
    }
    __syncthreads();

    u64 w = 0ull;
    if (g_bvalid[i]) {
        float x0 = g_bx0[i], y0 = g_by0[i], x1 = g_bx1[i], y1 = g_by1[i];
        float ar = g_barea[i];
        int jbase = cb * 64;
        #pragma unroll 8
        for (int b = 0; b < 64; b++) {
            int j = jbase + b;
            if (j > i) {
                float iw = fminf(x1, cx1[b]) - fmaxf(x0, cx0[b]) + 1.0f;
                float ih = fminf(y1, cy1[b]) - fmaxf(y0, cy0[b]) + 1.0f;
                iw = fmaxf(iw, 0.0f);
                ih = fmaxf(ih, 0.0f);
                float inter = iw * ih;
                float iou = inter / (ar + car[b] - inter);
                if (iou > NMS_T) w |= (1ull << b);
            }
        }
    }
    g_mask[(size_t)i * NWORD + cb] = w;
}

// ---------------- 5. pipelined greedy NMS + fused finalize ---------------------
// 128-row chunks, one barrier per chunk. Roles per iteration t:
//   tid 0         : greedy scan of chunk t (smem diag), fuses words 2t+2,2t+3
//   tid 1..31     : idle
//   tid 32..511   : bulk partial-OR for chunk t-1 kept rows (TPW threads/word,
//                   fixed (w,sub) smem slots; scan combines lazily)
//   tid 512..639  : prefetch chunk t+1 diag block into smem (double buffer)
#define RT 640
__global__ __launch_bounds__(RT) void nms_kernel(
        const int* __restrict__ labels, float* __restrict__ out) {
    __shared__ u64 sblk[2][128][4];
    __shared__ u64 part[NWORD][TPW];
    __shared__ u64 remv_s[NWORD + 3];
    __shared__ u64 vword[NWORD + 1];
    __shared__ u64 skw[NWORD + 1];
    __shared__ int kb[2][128];
    __shared__ int kcnt[2];
    __shared__ unsigned vhalf[NWORD * 2];

    const int tid  = threadIdx.x;
    const int lane = tid & 31;

    for (int i = tid; i < NWORD * TPW; i += RT) ((u64*)part)[i] = 0ull;
    for (int w = tid; w < NWORD + 3; w += RT) remv_s[w] = 0ull;
    for (int i = tid; i < NN; i += RT) {
        unsigned bal = __ballot_sync(0xFFFFFFFFu, g_bvalid[i] != 0u);
        if (lane == 0) vhalf[i >> 5] = bal;
    }
    if (tid == 0) { vword[NWORD] = 0ull; kcnt[0] = 0; kcnt[1] = 0; }
    __syncthreads();
    for (int w = tid; w < NWORD; w += RT)
        vword[w] = ((u64)vhalf[2*w+1] << 32) | (u64)vhalf[2*w];

    for (int e = tid; e < 512; e += RT) {        // prefetch chunk 0
        int r = e >> 2, wq = e & 3;
        sblk[0][r][wq] = g_mask[(size_t)r * NWORD + wq];
    }
    __syncthreads();

    for (int t = 0; t < NCH; t++) {
        const int p = t & 1;

        if (tid == 0) {
            u64 p0 = part[2*t][0] | part[2*t][1] | part[2*t][2]
                   | part[2*t][3] | part[2*t][4] | part[2*t][5];
            u64 p1 = part[2*t+1][0] | part[2*t+1][1] | part[2*t+1][2]
                   | part[2*t+1][3] | part[2*t+1][4] | part[2*t+1][5];
            u64 avail0 = vword[2*t]   & ~(remv_s[2*t]   | p0);
            u64 avail1 = vword[2*t+1] & ~(remv_s[2*t+1] | p1);
            u64 k0 = 0ull, k1 = 0ull, r2 = 0ull, r3 = 0ull;
            int n = 0;
            while (avail0 | avail1) {
                int b;
                if (avail0) {
                    b = __ffsll((long long)avail0) - 1;
                    k0 |= (1ull << b);
                    avail0 &= ~(1ull << b);
                } else {
                    int bb = __ffsll((long long)avail1) - 1;
                    b = 64 + bb;
                    k1 |= (1ull << bb);
                    avail1 &= ~(1ull << bb);
                }
                const u64* dd = sblk[p][b];
                avail0 &= ~dd[0];
                avail1 &= ~dd[1];
                r2 |= dd[2];
                r3 |= dd[3];
                kb[p][n++] = b;
            }
            kcnt[p] = n;
            skw[2*t]   = k0;
            skw[2*t+1] = k1;
            if (2*t+2 < NWORD) remv_s[2*t+2] |= r2;
            if (2*t+3 < NWORD) remv_s[2*t+3] |= r3;
        } else if (tid >= 32 && tid < 32 + 80 * TPW) {
            if (t > 0) {
                const int np = kcnt[p ^ 1];
                if (np > 0) {
                    int wi  = (tid - 32) / TPW;
                    int sub = (tid - 32) % TPW;
                    int w   = 2*t + 2 + wi;
                    if (w < NWORD && vword[w]) {
                        const int bRp  = (t - 1) * 128;
                        const int* kbp = kb[p ^ 1];
                        u64 acc = 0ull;
                        for (int q = sub; q < np; q += TPW)
                            acc |= g_mask[(size_t)(bRp + kbp[q]) * NWORD + w];
                        if (acc) part[w][sub] |= acc;
                    }
                }
            }
        } else if (tid >= 512) {
            const int tt = t + 1;
            if (tt < NCH && (vword[2*tt] | vword[2*tt+1])) {
                const int bR2 = tt * 128;
                for (int e = tid - 512; e < 512; e += RT - 512) {
                    int r = e >> 2, wq = e & 3;
                    int row = bR2 + r;
                    int gw  = 2*tt + wq;
                    u64 v = 0ull;
                    if (row < NN && gw < NWORD)
                        v = g_mask[(size_t)row * NWORD + gw];
                    sblk[p ^ 1][r][wq] = v;
                }
            }
        }
        __syncthreads();
    }

    // fused finalize
    for (int i = tid; i < NN; i += RT) {
        int nidx = g_order[i];
        unsigned kp = (unsigned)((skw[i >> 6] >> (i & 63)) & 1ull);
        float kf = kp ? 1.0f : 0.0f;
        float x0 = g_x0[nidx], y0 = g_y0[nidx];
        float wsv = g_ws[nidx], hsv = g_hs[nidx];
        out[6*NN + 4*nidx]     = (x0 + 0.5f * (wsv - 1.0f)) * kf;
        out[6*NN + 4*nidx + 1] = (y0 + 0.5f * (hsv - 1.0f)) * kf;
        out[6*NN + 4*nidx + 2] = wsv * kf;
        out[6*NN + 4*nidx + 3] = hsv * kf;
        out[10*NN + nidx] = g_prob[nidx] * kf;
        out[11*NN + nidx] = kp ? (float)labels[nidx] : 0.0f;
        out[12*NN + nidx] = kf;
    }
}

// -------------------------------------------------------------------------------
extern "C" void kernel_launch(void* const* d_in, const int* in_sizes, int n_in,
                              void* d_out, int out_size) {
    const float* x       = (const float*)d_in[0];
    const int*   labels  = (const int*)  d_in[1];
    const float* Wrpn    = (const float*)d_in[2];
    const float* brpn    = (const float*)d_in[3];
    const float* Wc      = (const float*)d_in[4];
    const float* bc      = (const float*)d_in[5];
    const float* Wr      = (const float*)d_in[6];
    const float* br      = (const float*)d_in[7];
    const float* anchors = (const float*)d_in[8];
    float* out = (float*)d_out;

    conv_part_kernel<<<dim3(FEAT, KCHUNKS), 576>>>(x, Wrpn);
    decode_kernel<<<NPIX / 32, 288>>>(Wc, bc, Wr, br, brpn, anchors, out);
    rank_part_kernel<<<dim3(18, NSLICE), 288>>>();
    scatter_rank_kernel<<<(NN + 255) / 256, 256>>>();
    mask_kernel<<<dim3(NWORD, NWORD), 64>>>();
    nms_kernel<<<1, RT>>>(labels, out);
}

// round 8
// speedup vs baseline: 2.2271x; 1.1412x over previous
#include <cuda_runtime.h>
#include <cuda_bf16.h>

#define FEAT   24
#define NPIX   (FEAT*FEAT)        // 576
#define KANCH  9
#define NN     (NPIX*KANCH)       // 5184
#define MIDCH  24
#define CINCH  512
#define NWORD  81
#define IMGW   384.0f
#define IMGH   384.0f
#define NMS_T  0.7f
#define MINSZ  16.0f
#define KCHUNKS 16
#define CPART  32
#define TPW    6

typedef unsigned long long u64;

// ---------------- scratch (device globals; zero-initialized) ------------------
__device__ float g_hpart[KCHUNKS * MIDCH * NPIX];

__device__ float g_x0[NN], g_y0[NN], g_ws[NN], g_hs[NN], g_prob[NN];
__device__ u64 g_ckeys[NN];          // compacted valid keys (low 32 = orig idx)
__device__ int g_vcount;

__device__ float g_bx0[NN], g_by0[NN], g_bx1[NN], g_by1[NN], g_barea[NN];
__device__ int g_order[NN];          // sorted pos -> original index

__device__ u64 g_mask[NN * NWORD];

// ---------------- 1. conv 3x3, 512->24, partial over K chunks -----------------
__global__ void conv_part_kernel(const float* __restrict__ x,
                                 const float* __restrict__ W) {
    const int y  = blockIdx.x;
    const int kc = blockIdx.y;
    const int c0 = kc * CPART;

    if (y == 0 && kc == 0 && threadIdx.x == 0) g_vcount = 0;  // reset per replay

    __shared__ float xs[CPART][3][26];
    __shared__ float ws[MIDCH][CPART][9];

    const int tid = threadIdx.x;        // 576

    for (int idx = tid; idx < CPART * 3 * 26; idx += 576) {
        int c  = idx / 78;
        int r  = (idx % 78) / 26;
        int xx = idx % 26;
        int gy = y + r - 1;
        int gx = xx - 1;
        float v = 0.0f;
        if (gy >= 0 && gy < FEAT && gx >= 0 && gx < FEAT)
            v = x[(c0 + c) * NPIX + gy * FEAT + gx];
        xs[c][r][xx] = v;
    }
    for (int idx = tid; idx < MIDCH * CPART * 9; idx += 576) {
        int o = idx / (CPART * 9);
        int c = (idx % (CPART * 9)) / 9;
        int t = idx % 9;
        ws[o][c][t] = W[((o * CINCH) + c0 + c) * 9 + t];
    }
    __syncthreads();

    const int xc = tid % FEAT;
    const int o  = tid / FEAT;
    float acc = 0.0f;
    #pragma unroll 4
    for (int c = 0; c < CPART; c++) {
        float a0 = xs[c][0][xc], a1 = xs[c][0][xc+1], a2 = xs[c][0][xc+2];
        float b0 = xs[c][1][xc], b1 = xs[c][1][xc+1], b2 = xs[c][1][xc+2];
        float d0 = xs[c][2][xc], d1 = xs[c][2][xc+1], d2 = xs[c][2][xc+2];
        const float* w = ws[o][c];
        acc += a0*w[0] + a1*w[1] + a2*w[2]
             + b0*w[3] + b1*w[4] + b2*w[5]
             + d0*w[6] + d1*w[7] + d2*w[8];
    }
    g_hpart[kc * (MIDCH*NPIX) + o * NPIX + y * FEAT + xc] = acc;
}

// ---------------- 2. heads + decode + valid compaction + default outputs ------
__global__ __launch_bounds__(288) void decode_kernel(
        const float* __restrict__ Wc, const float* __restrict__ bc,
        const float* __restrict__ Wr, const float* __restrict__ br,
        const float* __restrict__ brpn,
        const float* __restrict__ anchors,
        float* __restrict__ out) {
    __shared__ float sh[32][MIDCH];
    __shared__ float sWc[2*KANCH*MIDCH];
    __shared__ float sWr[4*KANCH*MIDCH];
    __shared__ float sbc[2*KANCH];
    __shared__ float sbr[4*KANCH];

    const int tid = threadIdx.x;
    const int p0  = blockIdx.x * 32;

    for (int i = tid; i < 32 * MIDCH; i += 288) {
        int ch = i / 32, pp = i % 32;
        float s = 0.0f;
        #pragma unroll
        for (int kc = 0; kc < KCHUNKS; kc++)
            s += g_hpart[kc * (MIDCH*NPIX) + ch * NPIX + p0 + pp];
        sh[pp][ch] = fmaxf(s + brpn[ch], 0.0f);
    }
    for (int i = tid; i < 2*KANCH*MIDCH; i += 288) sWc[i] = Wc[i];
    for (int i = tid; i < 4*KANCH*MIDCH; i += 288) sWr[i] = Wr[i];
    if (tid < 2*KANCH) sbc[tid] = bc[tid];
    if (tid < 4*KANCH) sbr[tid] = br[tid];
    __syncthreads();

    const int lp = tid / KANCH;
    const int k  = tid % KANCH;
    const int n  = (p0 + lp) * KANCH + k;

    float hv[MIDCH];
    #pragma unroll
    for (int o = 0; o < MIDCH; o++) hv[o] = sh[lp][o];

    float c0 = 0.0f, c1 = 0.0f;
    #pragma unroll
    for (int o = 0; o < MIDCH; o++) {
        c0 += hv[o] * sWc[(2*k)   * MIDCH + o];
        c1 += hv[o] * sWc[(2*k+1) * MIDCH + o];
    }
    c0 += sbc[2*k]; c1 += sbc[2*k+1];

    float tx = 0.0f, ty = 0.0f, tw = 0.0f, th = 0.0f;
    #pragma unroll
    for (int o = 0; o < MIDCH; o++) {
        float h = hv[o];
        tx += h * sWr[(4*k)   * MIDCH + o];
        ty += h * sWr[(4*k+1) * MIDCH + o];
        tw += h * sWr[(4*k+2) * MIDCH + o];
        th += h * sWr[(4*k+3) * MIDCH + o];
    }
    tx += sbr[4*k]; ty += sbr[4*k+1]; tw += sbr[4*k+2]; th += sbr[4*k+3];

    out[4*NN + 2*n]     = c0;
    out[4*NN + 2*n + 1] = c1;
    float prob = 1.0f / (1.0f + expf(c0 - c1));

    float ax = anchors[4*n],   ay = anchors[4*n+1];
    float aw = anchors[4*n+2], ah = anchors[4*n+3];

    float px = ax + aw * tx;
    float py = ay + ah * ty;
    float pw = aw * expf(tw);
    float ph = ah * expf(th);
    out[4*n]   = px; out[4*n+1] = py;
    out[4*n+2] = pw; out[4*n+3] = ph;

    float x0 = px - 0.5f * (pw - 1.0f);
    float y0 = py - 0.5f * (ph - 1.0f);
    float x1 = pw + x0 - 1.0f;
    float y1 = ph + y0 - 1.0f;
    x0 = fminf(fmaxf(x0, 0.0f), IMGW - 1.0f);
    x1 = fminf(fmaxf(x1, 0.0f), IMGW - 1.0f);
    y0 = fminf(fmaxf(y0, 0.0f), IMGH - 1.0f);
    y1 = fminf(fmaxf(y1, 0.0f), IMGH - 1.0f);
    float wsv = x1 - x0 + 1.0f;
    float hsv = y1 - y0 + 1.0f;

    float ax0 = ax - 0.5f * (aw - 1.0f);
    float ay0 = ay - 0.5f * (ah - 1.0f);
    float ax1 = aw + ax0 - 1.0f;
    float ay1 = ah + ay0 - 1.0f;
    bool anchor_valid = (ax0 >= 0.0f) && (ay0 >= 0.0f) && (ax1 < IMGW) && (ay1 < IMGH);
    bool valid = anchor_valid && (wsv >= MINSZ) && (hsv >= MINSZ);

    g_x0[n] = x0; g_y0[n] = y0;
    g_ws[n] = wsv; g_hs[n] = hsv; g_prob[n] = prob;

    // default (not-kept) outputs; NMS overwrites only kept rows
    out[6*NN + 4*n]     = 0.0f;
    out[6*NN + 4*n + 1] = 0.0f;
    out[6*NN + 4*n + 2] = 0.0f;
    out[6*NN + 4*n + 3] = 0.0f;
    out[10*NN + n] = 0.0f;
    out[11*NN + n] = 0.0f;
    out[12*NN + n] = 0.0f;

    if (valid) {
        float f = -prob;                               // valid scores only
        unsigned u = __float_as_uint(f);
        u = (u & 0x80000000u) ? ~u : (u | 0x80000000u);
        int pos = atomicAdd(&g_vcount, 1);
        g_ckeys[pos] = ((u64)u << 32) | (unsigned)n;
    }
}

// ---------------- 3. fused rank-sort + scatter over valid subset --------------
__global__ __launch_bounds__(288) void ranksort_kernel() {
    __shared__ u64 sk[NN];               // 41.5 KB
    const int V = g_vcount;
    if (blockIdx.x * 288 >= V) return;

    const int tid = threadIdx.x;
    for (int j = tid; j < V; j += 288) sk[j] = g_ckeys[j];
    __syncthreads();

    const int i = blockIdx.x * 288 + tid;
    if (i >= V) return;

    const u64 key = sk[i];
    int r = 0;
    #pragma unroll 4
    for (int j = 0; j < V; j++) r += (sk[j] < key) ? 1 : 0;

    const int n = (int)(unsigned)(key & 0xFFFFFFFFull);
    g_order[r]  = n;
    float x0 = g_x0[n], y0 = g_y0[n], wsv = g_ws[n], hsv = g_hs[n];
    g_bx0[r]   = x0;
    g_by0[r]   = y0;
    g_bx1[r]   = x0 + wsv - 1.0f;
    g_by1[r]   = y0 + hsv - 1.0f;
    g_barea[r] = wsv * hsv;
}

// ---------------- 4. suppression bitmask over valid rows only ------------------
__global__ void mask_kernel() {
    const int rb = blockIdx.y, cb = blockIdx.x;
    if (cb < rb) return;
    const int V = g_vcount;
    if (rb * 64 >= V || cb * 64 >= V) return;

    const int t = threadIdx.x;           // 64
    const int i = rb * 64 + t;

    __shared__ float cx0[64], cy0[64], cx1[64], cy1[64], car[64];
    {
        int j = cb * 64 + t;
        cx0[t] = g_bx0[j]; cy0[t] = g_by0[j];
        cx1[t] = g_bx1[j]; cy1[t] = g_by1[j];
        car[t] = g_barea[j];
    }
    __syncthreads();

    u64 w = 0ull;
    if (i < V) {
        float x0 = g_bx0[i], y0 = g_by0[i], x1 = g_bx1[i], y1 = g_by1[i];
        float ar = g_barea[i];
        int jbase = cb * 64;
        #pragma unroll 8
        for (int b = 0; b < 64; b++) {
            int j = jbase + b;
            if (j > i) {
                float iw = fminf(x1, cx1[b]) - fmaxf(x0, cx0[b]) + 1.0f;
                float ih = fminf(y1, cy1[b]) - fmaxf(y0, cy0[b]) + 1.0f;
                iw = fmaxf(iw, 0.0f);
                ih = fmaxf(ih, 0.0f);
                float inter = iw * ih;
                float iou = inter / (ar + car[b] - inter);
                if (iou > NMS_T) w |= (1ull << b);
            }
        }
    }
    g_mask[(size_t)i * NWORD + cb] = w;
}

// ---------------- 5. pipelined greedy NMS + kept-row finalize ------------------
#define RT 640
__global__ __launch_bounds__(RT) void nms_kernel(
        const int* __restrict__ labels, float* __restrict__ out) {
    __shared__ u64 sblk[2][128][4];
    __shared__ u64 part[NWORD][TPW];
    __shared__ u64 remv_s[NWORD + 3];
    __shared__ u64 vword[NWORD + 1];
    __shared__ u64 skw[NWORD + 1];
    __shared__ int kb[2][128];
    __shared__ int kcnt[2];

    const int tid = threadIdx.x;
    const int V   = g_vcount;
    const int NWORDv = (V + 63) >> 6;
    const int NCHv   = (V + 127) >> 7;

    for (int i = tid; i < NWORD * TPW; i += RT) ((u64*)part)[i] = 0ull;
    for (int w = tid; w < NWORD + 3; w += RT) remv_s[w] = 0ull;
    for (int w = tid; w < NWORD + 1; w += RT) {
        u64 v = 0ull;
        if ((w + 1) * 64 <= V) v = ~0ull;
        else if (w * 64 < V)   v = ((u64)1 << (V - w * 64)) - 1ull;
        vword[w] = v;
        skw[w] = 0ull;
    }
    if (tid == 0) { kcnt[0] = 0; kcnt[1] = 0; }

    for (int e = tid; e < 512; e += RT) {        // prefetch chunk 0
        int r = e >> 2, wq = e & 3;
        sblk[0][r][wq] = g_mask[(size_t)r * NWORD + wq];
    }
    __syncthreads();

    for (int t = 0; t < NCHv; t++) {
        const int p = t & 1;

        if (tid == 0) {
            u64 p0 = part[2*t][0] | part[2*t][1] | part[2*t][2]
                   | part[2*t][3] | part[2*t][4] | part[2*t][5];
            u64 p1 = part[2*t+1][0] | part[2*t+1][1] | part[2*t+1][2]
                   | part[2*t+1][3] | part[2*t+1][4] | part[2*t+1][5];
            u64 avail0 = vword[2*t]   & ~(remv_s[2*t]   | p0);
            u64 avail1 = vword[2*t+1] & ~(remv_s[2*t+1] | p1);
            u64 k0 = 0ull, k1 = 0ull, r2 = 0ull, r3 = 0ull;
            int n = 0;
            while (avail0 | avail1) {
                int b;
                if (avail0) {
                    b = __ffsll((long long)avail0) - 1;
                    k0 |= (1ull << b);
                    avail0 &= ~(1ull << b);
                } else {
                    int bb = __ffsll((long long)avail1) - 1;
                    b = 64 + bb;
                    k1 |= (1ull << bb);
                    avail1 &= ~(1ull << bb);
                }
                const u64* dd = sblk[p][b];
                avail0 &= ~dd[0];
                avail1 &= ~dd[1];
                r2 |= dd[2];
                r3 |= dd[3];
                kb[p][n++] = b;
            }
            kcnt[p] = n;
            skw[2*t]   = k0;
            skw[2*t+1] = k1;
            remv_s[2*t+2] |= r2;
            remv_s[2*t+3] |= r3;
        } else if (tid >= 32 && tid < 32 + 80 * TPW) {
            if (t > 0) {
                const int np = kcnt[p ^ 1];
                if (np > 0) {
                    int wi  = (tid - 32) / TPW;
                    int sub = (tid - 32) % TPW;
                    int w   = 2*t + 2 + wi;
                    if (w < NWORDv && vword[w]) {
                        const int bRp  = (t - 1) * 128;
                        const int* kbp = kb[p ^ 1];
                        u64 acc = 0ull;
                        for (int q = sub; q < np; q += TPW)
                            acc |= g_mask[(size_t)(bRp + kbp[q]) * NWORD + w];
                        if (acc) part[w][sub] |= acc;
                    }
                }
            }
        } else if (tid >= 512) {
            const int tt = t + 1;
            if (tt < NCHv) {
                const int bR2 = tt * 128;
                for (int e = tid - 512; e < 512; e += RT - 512) {
                    int r = e >> 2, wq = e & 3;
                    int row = bR2 + r;
                    int gw  = 2*tt + wq;
                    u64 v = 0ull;
                    if (row < NN && gw < NWORD)
                        v = g_mask[(size_t)row * NWORD + gw];
                    sblk[p ^ 1][r][wq] = v;
                }
            }
        }
        __syncthreads();
    }

    // finalize kept rows only (defaults already written by decode)
    for (int i = tid; i < V; i += RT) {
        if ((skw[i >> 6] >> (i & 63)) & 1ull) {
            int n = g_order[i];
            float x0 = g_x0[n], y0 = g_y0[n];
            float wsv = g_ws[n], hsv = g_hs[n];
            out[6*NN + 4*n]     = x0 + 0.5f * (wsv - 1.0f);
            out[6*NN + 4*n + 1] = y0 + 0.5f * (hsv - 1.0f);
            out[6*NN + 4*n + 2] = wsv;
            out[6*NN + 4*n + 3] = hsv;
            out[10*NN + n] = g_prob[n];
            out[11*NN + n] = (float)labels[n];
            out[12*NN + n] = 1.0f;
        }
    }
}

// -------------------------------------------------------------------------------
extern "C" void kernel_launch(void* const* d_in, const int* in_sizes, int n_in,
                              void* d_out, int out_size) {
    const float* x       = (const float*)d_in[0];
    const int*   labels  = (const int*)  d_in[1];
    const float* Wrpn    = (const float*)d_in[2];
    const float* brpn    = (const float*)d_in[3];
    const float* Wc      = (const float*)d_in[4];
    const float* bc      = (const float*)d_in[5];
    const float* Wr      = (const float*)d_in[6];
    const float* br      = (const float*)d_in[7];
    const float* anchors = (const float*)d_in[8];
    float* out = (float*)d_out;

    conv_part_kernel<<<dim3(FEAT, KCHUNKS), 576>>>(x, Wrpn);
    decode_kernel<<<NPIX / 32, 288>>>(Wc, bc, Wr, br, brpn, anchors, out);
    ranksort_kernel<<<18, 288>>>();
    mask_kernel<<<dim3(NWORD, NWORD), 64>>>();
    nms_kernel<<<1, RT>>>(labels, out);
}